// round 11
// baseline (speedup 1.0000x reference)
#include <cuda_runtime.h>
#include <cuda_fp16.h>
#include <cstdint>
#include <cstddef>

#define KDIM 256
#define NQ_  1024
#define B_   4
#define NF_  65536

// scratch (__device__ globals: the sanctioned no-alloc path)
__device__ __half g_qh[NQ_ * KDIM];        // fp16 MLP output (logits B operand)

__device__ __forceinline__ uint32_t cvta_s(const void* p) {
    return (uint32_t)__cvta_generic_to_shared(p);
}

#define LDM4(r0, r1, r2, r3, addr) \
    asm volatile("ldmatrix.sync.aligned.m8n8.x4.shared.b16 {%0,%1,%2,%3}, [%4];" \
                 : "=r"(r0), "=r"(r1), "=r"(r2), "=r"(r3) : "r"(addr))

#define MMA16(c, a, b0, b1) \
    asm volatile("mma.sync.aligned.m16n8k16.row.col.f32.f16.f16.f32 " \
                 "{%0,%1,%2,%3},{%4,%5,%6,%7},{%8,%9},{%0,%1,%2,%3};" \
                 : "+f"((c)[0]), "+f"((c)[1]), "+f"((c)[2]), "+f"((c)[3]) \
                 : "r"((a)[0]), "r"((a)[1]), "r"((a)[2]), "r"((a)[3]), "r"(b0), "r"(b1))

#define CP16(dst, src) \
    asm volatile("cp.async.cg.shared.global [%0], [%1], 16;" :: "r"(dst), "l"(src))

#define LDS64(lo, hi, addr) \
    asm volatile("ld.shared.v2.b32 {%0,%1}, [%2];" : "=r"(lo), "=r"(hi) : "r"(addr))

// ---------------------------------------------------------------------------
// Fused 4-layer MLP, now consuming RAW f32 weights (prep_w eliminated).
//  - x ping-pongs in SMEM as fp16 (swizzled, ldmatrix A-fragments)
//  - W streamed as f32 via 3-slot cp.async ring (32KB/slot);
//    B-fragments built with conflict-free LDS.64 + cvt (R8-validated pattern)
//  - final layer writes fp16 qh (logits B operand)
//  W slot layout: row n (0..255) x 32 f32; byte = n*128 + ((c ^ (n&7))*16), c=0..7
// ---------------------------------------------------------------------------
#define MLP_SMEM (65536 + 3 * 32768 + 4096)   // x(2x32K) + Wring(3x32K) + bias

__global__ __launch_bounds__(256) void mlp_fused(
    const float* __restrict__ Q,
    const float* __restrict__ W1f, const float* __restrict__ W2f,
    const float* __restrict__ W3f, const float* __restrict__ W4f,
    const float* __restrict__ b1, const float* __restrict__ b2,
    const float* __restrict__ b3, const float* __restrict__ b4,
    __half* __restrict__ qh)
{
    extern __shared__ char sm[];
    char*  xb = sm;                          // 2 x 32768 (fp16 x)
    char*  ws = sm + 65536;                  // 3 x 32768 (f32 W ring)
    float* sb = (float*)(sm + 65536 + 98304);

    const int tid = threadIdx.x;
    const int w = tid >> 5, l = tid & 31;
    const int g = l >> 2, t = l & 3;
    const int wm = (w & 1) * 32;     // 2 m-warps
    const int wn = (w >> 1) * 64;    // 4 n-warps
    const int m0 = blockIdx.x * 64;

    sb[tid] = b1[tid]; sb[256 + tid] = b2[tid];
    sb[512 + tid] = b3[tid]; sb[768 + tid] = b4[tid];

    // queries f32 -> fp16 swizzled into xb[0]
#pragma unroll
    for (int i = 0; i < 16; i++) {
        int idx = tid + i * 256;
        int r = idx >> 6, k = (idx & 63) * 4;
        float4 v = *(const float4*)&Q[(size_t)(m0 + r) * KDIM + k];
        __half2 h0 = __floats2half2_rn(v.x, v.y);
        __half2 h1 = __floats2half2_rn(v.z, v.w);
        int chunk = k >> 5, c16 = (k & 31) >> 3, hi = (k >> 2) & 1;
        uint32_t ad = cvta_s(xb + chunk * 4096 + (r & 31) * 128
                             + ((((r >> 5) * 4) + c16) ^ (r & 7)) * 16 + hi * 8);
        asm volatile("st.shared.v2.b32 [%0], {%1,%2};"
                     :: "r"(ad), "r"(*(uint32_t*)&h0), "r"(*(uint32_t*)&h1));
    }

    // W cp.async dsts: thread = row n=tid, 8 x 16B f32 chunks
    uint32_t wst[8];
#pragma unroll
    for (int c = 0; c < 8; c++)
        wst[c] = cvta_s(ws + tid * 128 + ((c ^ (tid & 7)) * 16));

    // W fragment addressing: row bases + per-(g16,h) in-row offsets
    uint32_t wrow[8];
#pragma unroll
    for (int nt = 0; nt < 8; nt++)
        wrow[nt] = cvta_s(ws + (wn + nt * 8 + g) * 128);
    uint32_t woff[2][2];
#pragma unroll
    for (int g16 = 0; g16 < 2; g16++)
#pragma unroll
        for (int h = 0; h < 2; h++)
            woff[g16][h] = (uint32_t)((((g16 * 4 + h * 2 + (t >> 1)) ^ g) * 16) + (t & 1) * 8);

    __syncthreads();

    const float* Wf[4] = {W1f, W2f, W3f, W4f};

    for (int L = 0; L < 4; L++) {
        const float* Wl = Wf[L];
        const uint32_t xbase = (uint32_t)(L & 1) * 32768;

        uint32_t a_addr[2];
        {
            int r = wm + (l & 7) + ((l >> 3) & 1) * 8;
            int ck = (l >> 4) & 1;
#pragma unroll
            for (int mt = 0; mt < 2; mt++) {
                int rr = r + mt * 16;
                int cp = (((rr >> 5) * 4 + ck) ^ (rr & 7));
                a_addr[mt] = cvta_s(xb + xbase + (rr & 31) * 128 + cp * 16);
            }
        }

        // prologue: W chunks 0,1 (f32)
#pragma unroll
        for (int s = 0; s < 2; s++) {
#pragma unroll
            for (int c = 0; c < 8; c++)
                CP16(wst[c] + s * 32768, Wl + (size_t)tid * KDIM + s * 32 + c * 4);
            asm volatile("cp.async.commit_group;");
        }

        float acc[2][8][4];
#pragma unroll
        for (int mt = 0; mt < 2; mt++)
#pragma unroll
            for (int nt = 0; nt < 8; nt++)
#pragma unroll
                for (int i = 0; i < 4; i++) acc[mt][nt][i] = 0.f;

#pragma unroll
        for (int kt = 0; kt < 8; kt++) {
            asm volatile("cp.async.wait_group 1;");
            __syncthreads();
            if (kt < 6) {
                int s = (kt + 2) % 3;
#pragma unroll
                for (int c = 0; c < 8; c++)
                    CP16(wst[c] + s * 32768, Wl + (size_t)tid * KDIM + (kt + 2) * 32 + c * 4);
            }
            asm volatile("cp.async.commit_group;");

            const uint32_t abuf = kt * 4096;
            const uint32_t wslot = (uint32_t)(kt % 3) * 32768;
#pragma unroll
            for (int g16 = 0; g16 < 2; g16++) {
                const uint32_t xo = g16 * 32;
                uint32_t a0[4], a1[4];
                LDM4(a0[0], a0[1], a0[2], a0[3], (a_addr[0] + abuf) ^ xo);
                LDM4(a1[0], a1[1], a1[2], a1[3], (a_addr[1] + abuf) ^ xo);
#pragma unroll
                for (int nt = 0; nt < 8; nt++) {
                    uint32_t q0, q1;
                    {
                        uint32_t lo, hi;
                        LDS64(lo, hi, wrow[nt] + wslot + woff[g16][0]);
                        __half2 hh = __floats2half2_rn(__uint_as_float(lo), __uint_as_float(hi));
                        q0 = *(uint32_t*)&hh;
                        LDS64(lo, hi, wrow[nt] + wslot + woff[g16][1]);
                        __half2 hh1 = __floats2half2_rn(__uint_as_float(lo), __uint_as_float(hi));
                        q1 = *(uint32_t*)&hh1;
                    }
                    MMA16(acc[0][nt], a0, q0, q1);
                    MMA16(acc[1][nt], a1, q0, q1);
                }
            }
        }

        __syncthreads();

        if (L < 3) {
            const uint32_t pong = (uint32_t)((L & 1) ^ 1) * 32768;
#pragma unroll
            for (int mt = 0; mt < 2; mt++) {
#pragma unroll
                for (int nt = 0; nt < 8; nt++) {
                    int r = wm + mt * 16 + g;
                    int c = wn + nt * 8 + 2 * t;
                    float bi0 = sb[L * 256 + c], bi1 = sb[L * 256 + c + 1];
                    float v0 = fmaxf(acc[mt][nt][0] + bi0, 0.f);
                    float v1 = fmaxf(acc[mt][nt][1] + bi1, 0.f);
                    float v2 = fmaxf(acc[mt][nt][2] + bi0, 0.f);
                    float v3 = fmaxf(acc[mt][nt][3] + bi1, 0.f);
                    __half2 h01 = __floats2half2_rn(v0, v1);
                    __half2 h23 = __floats2half2_rn(v2, v3);
                    int chunk = c >> 5, c16 = (c & 31) >> 3, bo = (c & 7) * 2;
                    int r8 = r + 8;
                    uint32_t ad0 = cvta_s(xb + pong + chunk * 4096 + (r & 31) * 128
                                   + ((((r >> 5) * 4) + c16) ^ (r & 7)) * 16 + bo);
                    uint32_t ad1 = cvta_s(xb + pong + chunk * 4096 + (r8 & 31) * 128
                                   + ((((r8 >> 5) * 4) + c16) ^ (r8 & 7)) * 16 + bo);
                    asm volatile("st.shared.b32 [%0], %1;" :: "r"(ad0), "r"(*(uint32_t*)&h01));
                    asm volatile("st.shared.b32 [%0], %1;" :: "r"(ad1), "r"(*(uint32_t*)&h23));
                }
            }
        } else {
#pragma unroll
            for (int mt = 0; mt < 2; mt++) {
#pragma unroll
                for (int nt = 0; nt < 8; nt++) {
                    int r = m0 + wm + mt * 16 + g;
                    int c = wn + nt * 8 + 2 * t;
                    float bi0 = sb[768 + c], bi1 = sb[768 + c + 1];
                    __half2 h01 = __floats2half2_rn(acc[mt][nt][0] + bi0, acc[mt][nt][1] + bi1);
                    __half2 h23 = __floats2half2_rn(acc[mt][nt][2] + bi0, acc[mt][nt][3] + bi1);
                    *(__half2*)&qh[(size_t)r * KDIM + c]       = h01;
                    *(__half2*)&qh[(size_t)(r + 8) * KDIM + c] = h23;
                }
            }
        }
        __syncthreads();
    }
}

// ---------------------------------------------------------------------------
// Logits GEMM — EXACT round-7 version (best measured: ~183us component).
// ---------------------------------------------------------------------------
#define LOG_SMEM (2 * 8192 + 4 * 8192)   // 49152

__global__ __launch_bounds__(256)
void gemm_logits(const float* __restrict__ A, const __half* __restrict__ Bh,
                 float* __restrict__ C)
{
    extern __shared__ char sm[];
    char* As_ = sm;            // 2 x 8192
    char* Bs_ = sm + 16384;    // 4 x 8192

    const int tid = threadIdx.x;
    const int w = tid >> 5, l = tid & 31;
    const int g = l >> 2, t = l & 3;
    const int wm = (w & 3) * 32;
    const int wn = (w >> 2) * 64;

    const int nb = blockIdx.x;   // n-inner: nb pair shares the A tile via L2
    const int mb = blockIdx.y;
    const long long bb = blockIdx.z;

    const float* Ab = A + bb * ((long long)NF_ * KDIM) + (size_t)mb * 128 * KDIM;
    const __half* Bb = Bh + bb * ((long long)256 * KDIM) + (size_t)nb * 128 * KDIM;
    float* Cb = C + bb * ((long long)NF_ * 256) + (size_t)mb * 128 * 256 + (size_t)nb * 128;

    uint32_t a_addr[2];
    {
        int r = wm + (l & 7) + ((l >> 3) & 1) * 8;
        int ck = (l >> 4) & 1;
#pragma unroll
        for (int mt = 0; mt < 2; mt++) {
            int rr = r + mt * 16;
            int cp = (((rr >> 6) * 4 + ck) ^ (rr & 7));
            a_addr[mt] = cvta_s(As_ + (rr & 63) * 128 + cp * 16);
        }
    }
    uint32_t b_addr[4];
    {
        int n = wn + (l & 7) + ((l >> 4) & 1) * 8;
        int ck = (l >> 3) & 1;
#pragma unroll
        for (int p = 0; p < 4; p++) {
            int nn = n + p * 16;
            int cp = (((nn >> 6) * 4 + ck) ^ (nn & 7));
            b_addr[p] = cvta_s(Bs_ + (nn & 63) * 128 + cp * 16);
        }
    }
    const int fA = tid & 7;
    uint32_t sts_addr[4];
    const float* aload[4];
#pragma unroll
    for (int i = 0; i < 4; i++) {
        int r = i * 32 + (tid >> 3);
        int cp = (((r >> 6) * 4 + (fA >> 1)) ^ (r & 7));
        sts_addr[i] = cvta_s(As_ + (r & 63) * 128 + cp * 16 + (fA & 1) * 8);
        aload[i] = Ab + (size_t)r * KDIM + fA * 4;
    }
    uint32_t bst_addr[2];
    const __half* bld[2];
#pragma unroll
    for (int i = 0; i < 2; i++) {
        int cid = tid * 2 + i;
        int n = cid >> 2, c = cid & 3;
        int cp = (((n >> 6) * 4 + c) ^ (n & 7));
        bst_addr[i] = cvta_s(Bs_ + (n & 63) * 128 + cp * 16);
        bld[i] = Bb + (size_t)n * KDIM + c * 8;
    }

    // ---- prologue ----
    float4 pre[2][4];
#pragma unroll
    for (int i = 0; i < 4; i++) pre[0][i] = *(const float4*)(aload[i]);          // A(0)
#pragma unroll
    for (int i = 0; i < 2; i++) CP16(bst_addr[i], bld[i]);                       // B(0)
    asm volatile("cp.async.commit_group;");
#pragma unroll
    for (int i = 0; i < 4; i++) pre[1][i] = *(const float4*)(aload[i] + 32);     // A(1)
#pragma unroll
    for (int i = 0; i < 2; i++) CP16(bst_addr[i] + 8192, bld[i] + 32);           // B(1)
    asm volatile("cp.async.commit_group;");
#pragma unroll
    for (int i = 0; i < 2; i++) CP16(bst_addr[i] + 16384, bld[i] + 64);          // B(2)
    asm volatile("cp.async.commit_group;");

#pragma unroll
    for (int i = 0; i < 4; i++) {
        __half2 h0 = __floats2half2_rn(pre[0][i].x, pre[0][i].y);
        __half2 h1 = __floats2half2_rn(pre[0][i].z, pre[0][i].w);
        asm volatile("st.shared.v2.b32 [%0], {%1,%2};"
                     :: "r"(sts_addr[i]), "r"(*(uint32_t*)&h0), "r"(*(uint32_t*)&h1));
    }

    float acc[2][8][4];
#pragma unroll
    for (int mt = 0; mt < 2; mt++)
#pragma unroll
        for (int nt = 0; nt < 8; nt++)
#pragma unroll
            for (int i = 0; i < 4; i++) acc[mt][nt][i] = 0.f;

    asm volatile("cp.async.wait_group 2;");   // B(0) resident
    __syncthreads();

#pragma unroll
    for (int kt = 0; kt < 8; kt++) {
        const uint32_t abuf = (kt & 1) * 8192;
        const uint32_t bbuf = (kt & 3) * 8192;

        uint32_t a0[2][4];
        LDM4(a0[0][0], a0[0][1], a0[0][2], a0[0][3], a_addr[0] + abuf);
        LDM4(a0[1][0], a0[1][1], a0[1][2], a0[1][3], a_addr[1] + abuf);
        uint32_t bf0[4][4];
#pragma unroll
        for (int p = 0; p < 4; p++)
            LDM4(bf0[p][0], bf0[p][1], bf0[p][2], bf0[p][3], b_addr[p] + bbuf);

        if (kt < 7) {
            const uint32_t nab = ((kt + 1) & 1) * 8192;
#pragma unroll
            for (int i = 0; i < 4; i++) {
                __half2 h0 = __floats2half2_rn(pre[(kt + 1) & 1][i].x, pre[(kt + 1) & 1][i].y);
                __half2 h1 = __floats2half2_rn(pre[(kt + 1) & 1][i].z, pre[(kt + 1) & 1][i].w);
                asm volatile("st.shared.v2.b32 [%0], {%1,%2};"
                             :: "r"(sts_addr[i] + nab),
                                "r"(*(uint32_t*)&h0), "r"(*(uint32_t*)&h1));
            }
        }

        uint32_t a1[2][4];
        LDM4(a1[0][0], a1[0][1], a1[0][2], a1[0][3], (a_addr[0] + abuf) ^ 32);
        LDM4(a1[1][0], a1[1][1], a1[1][2], a1[1][3], (a_addr[1] + abuf) ^ 32);
        uint32_t bf1[4][4];
#pragma unroll
        for (int p = 0; p < 4; p++)
            LDM4(bf1[p][0], bf1[p][1], bf1[p][2], bf1[p][3], (b_addr[p] + bbuf) ^ 32);

        if (kt < 6) {
#pragma unroll
            for (int i = 0; i < 4; i++)
                pre[kt & 1][i] = *(const float4*)(aload[i] + (kt + 2) * 32);
        }

#pragma unroll
        for (int nt = 0; nt < 8; nt++) {
            uint32_t q0 = bf0[nt >> 1][(nt & 1) * 2];
            uint32_t q1 = bf0[nt >> 1][(nt & 1) * 2 + 1];
            MMA16(acc[0][nt], a0[0], q0, q1);
            MMA16(acc[1][nt], a0[1], q0, q1);
        }

        if (kt < 5) {
            const uint32_t ns = ((kt + 3) & 3) * 8192;
#pragma unroll
            for (int i = 0; i < 2; i++)
                CP16(bst_addr[i] + ns, bld[i] + (kt + 3) * 32);
        }
        asm volatile("cp.async.commit_group;");
        asm volatile("cp.async.wait_group 2;");

#pragma unroll
        for (int nt = 0; nt < 8; nt++) {
            uint32_t q0 = bf1[nt >> 1][(nt & 1) * 2];
            uint32_t q1 = bf1[nt >> 1][(nt & 1) * 2 + 1];
            MMA16(acc[0][nt], a1[0], q0, q1);
            MMA16(acc[1][nt], a1[1], q0, q1);
        }

        __syncthreads();
    }

#pragma unroll
    for (int mt = 0; mt < 2; mt++) {
        const int r0 = wm + mt * 16 + g;
#pragma unroll
        for (int nt = 0; nt < 8; nt++) {
            const int c = wn + nt * 8 + 2 * t;
            __stcs((float2*)&Cb[(size_t)r0 * 256 + c],
                   make_float2(acc[mt][nt][0], acc[mt][nt][1]));
            __stcs((float2*)&Cb[(size_t)(r0 + 8) * 256 + c],
                   make_float2(acc[mt][nt][2], acc[mt][nt][3]));
        }
    }
}

// ---------------------------------------------------------------------------
extern "C" void kernel_launch(void* const* d_in, const int* in_sizes, int n_in,
                              void* d_out, int out_size)
{
    (void)in_sizes; (void)n_in; (void)out_size;
    const float* queries = (const float*)d_in[0];
    const float* feats   = (const float*)d_in[1];
    const float* W1 = (const float*)d_in[4];
    const float* b1 = (const float*)d_in[5];
    const float* W2 = (const float*)d_in[6];
    const float* b2 = (const float*)d_in[7];
    const float* W3 = (const float*)d_in[8];
    const float* b3 = (const float*)d_in[9];
    const float* W4 = (const float*)d_in[10];
    const float* b4 = (const float*)d_in[11];
    float* out = (float*)d_out;

    __half* qh = nullptr;
    cudaGetSymbolAddress((void**)&qh, g_qh);

    cudaFuncSetAttribute(mlp_fused,   cudaFuncAttributeMaxDynamicSharedMemorySize, MLP_SMEM);
    cudaFuncSetAttribute(gemm_logits, cudaFuncAttributeMaxDynamicSharedMemorySize, LOG_SMEM);

    mlp_fused<<<16, 256, MLP_SMEM>>>(queries, W1, W2, W3, W4, b1, b2, b3, b4, qh);
    gemm_logits<<<dim3(2, NF_ / 128, B_), 256, LOG_SMEM>>>(feats, qh, out);
}

// round 12
// speedup vs baseline: 1.1825x; 1.1825x over previous
#include <cuda_runtime.h>
#include <cuda_fp16.h>
#include <cstdint>
#include <cstddef>

#define KDIM 256
#define NQ_  1024
#define B_   4
#define NF_  65536

// scratch (__device__ globals: the sanctioned no-alloc path)
__device__ __half g_wh[4 * KDIM * KDIM];   // fp16 weights, [layer][out][in]
__device__ __half g_qh[NQ_ * KDIM];        // fp16 MLP output (logits B operand)

__device__ __forceinline__ uint32_t cvta_s(const void* p) {
    return (uint32_t)__cvta_generic_to_shared(p);
}

#define LDM4(r0, r1, r2, r3, addr) \
    asm volatile("ldmatrix.sync.aligned.m8n8.x4.shared.b16 {%0,%1,%2,%3}, [%4];" \
                 : "=r"(r0), "=r"(r1), "=r"(r2), "=r"(r3) : "r"(addr))

#define MMA16(c, a, b0, b1) \
    asm volatile("mma.sync.aligned.m16n8k16.row.col.f32.f16.f16.f32 " \
                 "{%0,%1,%2,%3},{%4,%5,%6,%7},{%8,%9},{%0,%1,%2,%3};" \
                 : "+f"((c)[0]), "+f"((c)[1]), "+f"((c)[2]), "+f"((c)[3]) \
                 : "r"((a)[0]), "r"((a)[1]), "r"((a)[2]), "r"((a)[3]), "r"(b0), "r"(b1))

#define CP16(dst, src) \
    asm volatile("cp.async.cg.shared.global [%0], [%1], 16;" :: "r"(dst), "l"(src))

// ---------------------------------------------------------------------------
// prep: convert the 4 weight matrices f32 -> fp16 (once per launch)
// ---------------------------------------------------------------------------
__global__ void prep_w(const float* __restrict__ W1, const float* __restrict__ W2,
                       const float* __restrict__ W3, const float* __restrict__ W4)
{
    int idx = blockIdx.x * 256 + threadIdx.x;          // 65536 float4 total
    const float* src = (idx < 16384) ? W1 : (idx < 32768) ? W2 : (idx < 49152) ? W3 : W4;
    int off = idx & 16383;
    float4 v = ((const float4*)src)[off];
    __half2 h0 = __floats2half2_rn(v.x, v.y);
    __half2 h1 = __floats2half2_rn(v.z, v.w);
    uint2 u;
    u.x = *(uint32_t*)&h0;
    u.y = *(uint32_t*)&h1;
    ((uint2*)g_wh)[idx] = u;
}

// ---------------------------------------------------------------------------
// Fused 4-layer MLP (R7 version, fp16 weights; ~15us)
// ---------------------------------------------------------------------------
#define MLP_SMEM (65536 + 49152 + 4096)

__global__ __launch_bounds__(256) void mlp_fused(
    const float* __restrict__ Q, const __half* __restrict__ wh,
    const float* __restrict__ b1, const float* __restrict__ b2,
    const float* __restrict__ b3, const float* __restrict__ b4,
    __half* __restrict__ qh)
{
    extern __shared__ char sm[];
    char*  xb = sm;                        // 2 x 32768
    char*  ws = sm + 65536;                // 3 x 16384
    float* sb = (float*)(sm + 65536 + 49152);

    const int tid = threadIdx.x;
    const int w = tid >> 5, l = tid & 31;
    const int g = l >> 2, t = l & 3;
    const int wm = (w & 1) * 32;
    const int wn = (w >> 1) * 64;
    const int m0 = blockIdx.x * 64;

    sb[tid] = b1[tid]; sb[256 + tid] = b2[tid];
    sb[512 + tid] = b3[tid]; sb[768 + tid] = b4[tid];

#pragma unroll
    for (int i = 0; i < 16; i++) {
        int idx = tid + i * 256;
        int r = idx >> 6, k = (idx & 63) * 4;
        float4 v = *(const float4*)&Q[(size_t)(m0 + r) * KDIM + k];
        __half2 h0 = __floats2half2_rn(v.x, v.y);
        __half2 h1 = __floats2half2_rn(v.z, v.w);
        int chunk = k >> 5, c16 = (k & 31) >> 3, hi = (k >> 2) & 1;
        uint32_t ad = cvta_s(xb + chunk * 4096 + (r & 31) * 128
                             + ((((r >> 5) * 4) + c16) ^ (r & 7)) * 16 + hi * 8);
        asm volatile("st.shared.v2.b32 [%0], {%1,%2};"
                     :: "r"(ad), "r"(*(uint32_t*)&h0), "r"(*(uint32_t*)&h1));
    }

    uint32_t b_addr[4];
    {
        int n = wn + (l & 7) + ((l >> 4) & 1) * 8;
        int ck = (l >> 3) & 1;
#pragma unroll
        for (int p = 0; p < 4; p++) {
            int nn = n + p * 16;
            int cp = (((nn >> 7) * 4 + ck) ^ (nn & 7));
            b_addr[p] = cvta_s(ws + (nn & 127) * 128 + cp * 16);
        }
    }
    uint32_t wst[4];
#pragma unroll
    for (int c = 0; c < 4; c++) {
        int n = tid;
        wst[c] = cvta_s(ws + (n & 127) * 128 + ((((n >> 7) * 4) + c) ^ (n & 7)) * 16);
    }

    __syncthreads();

    for (int L = 0; L < 4; L++) {
        const __half* Wl = wh + (size_t)L * 65536;
        const uint32_t xbase = (uint32_t)(L & 1) * 32768;

        uint32_t a_addr[2];
        {
            int r = wm + (l & 7) + ((l >> 3) & 1) * 8;
            int ck = (l >> 4) & 1;
#pragma unroll
            for (int mt = 0; mt < 2; mt++) {
                int rr = r + mt * 16;
                int cp = (((rr >> 5) * 4 + ck) ^ (rr & 7));
                a_addr[mt] = cvta_s(xb + xbase + (rr & 31) * 128 + cp * 16);
            }
        }

#pragma unroll
        for (int s = 0; s < 2; s++) {
#pragma unroll
            for (int c = 0; c < 4; c++)
                CP16(wst[c] + s * 16384, Wl + (size_t)tid * KDIM + s * 32 + c * 8);
            asm volatile("cp.async.commit_group;");
        }

        float acc[2][8][4];
#pragma unroll
        for (int mt = 0; mt < 2; mt++)
#pragma unroll
            for (int nt = 0; nt < 8; nt++)
#pragma unroll
                for (int i = 0; i < 4; i++) acc[mt][nt][i] = 0.f;

#pragma unroll
        for (int kt = 0; kt < 8; kt++) {
            asm volatile("cp.async.wait_group 1;");
            __syncthreads();
            if (kt < 6) {
                int s = (kt + 2) % 3;
#pragma unroll
                for (int c = 0; c < 4; c++)
                    CP16(wst[c] + s * 16384, Wl + (size_t)tid * KDIM + (kt + 2) * 32 + c * 8);
            }
            asm volatile("cp.async.commit_group;");

            const uint32_t abuf = kt * 4096;
            const uint32_t bbuf = (kt % 3) * 16384;
#pragma unroll
            for (int g16 = 0; g16 < 2; g16++) {
                const uint32_t xo = g16 * 32;
                uint32_t a0[4], a1[4];
                LDM4(a0[0], a0[1], a0[2], a0[3], (a_addr[0] + abuf) ^ xo);
                LDM4(a1[0], a1[1], a1[2], a1[3], (a_addr[1] + abuf) ^ xo);
                uint32_t bf[4][4];
#pragma unroll
                for (int p = 0; p < 4; p++)
                    LDM4(bf[p][0], bf[p][1], bf[p][2], bf[p][3], (b_addr[p] + bbuf) ^ xo);
#pragma unroll
                for (int nt = 0; nt < 8; nt++) {
                    uint32_t q0 = bf[nt >> 1][(nt & 1) * 2];
                    uint32_t q1 = bf[nt >> 1][(nt & 1) * 2 + 1];
                    MMA16(acc[0][nt], a0, q0, q1);
                    MMA16(acc[1][nt], a1, q0, q1);
                }
            }
        }

        __syncthreads();

        if (L < 3) {
            const uint32_t pong = (uint32_t)((L & 1) ^ 1) * 32768;
#pragma unroll
            for (int mt = 0; mt < 2; mt++) {
#pragma unroll
                for (int nt = 0; nt < 8; nt++) {
                    int r = wm + mt * 16 + g;
                    int c = wn + nt * 8 + 2 * t;
                    float bi0 = sb[L * 256 + c], bi1 = sb[L * 256 + c + 1];
                    float v0 = fmaxf(acc[mt][nt][0] + bi0, 0.f);
                    float v1 = fmaxf(acc[mt][nt][1] + bi1, 0.f);
                    float v2 = fmaxf(acc[mt][nt][2] + bi0, 0.f);
                    float v3 = fmaxf(acc[mt][nt][3] + bi1, 0.f);
                    __half2 h01 = __floats2half2_rn(v0, v1);
                    __half2 h23 = __floats2half2_rn(v2, v3);
                    int chunk = c >> 5, c16 = (c & 31) >> 3, bo = (c & 7) * 2;
                    int r8 = r + 8;
                    uint32_t ad0 = cvta_s(xb + pong + chunk * 4096 + (r & 31) * 128
                                   + ((((r >> 5) * 4) + c16) ^ (r & 7)) * 16 + bo);
                    uint32_t ad1 = cvta_s(xb + pong + chunk * 4096 + (r8 & 31) * 128
                                   + ((((r8 >> 5) * 4) + c16) ^ (r8 & 7)) * 16 + bo);
                    asm volatile("st.shared.b32 [%0], %1;" :: "r"(ad0), "r"(*(uint32_t*)&h01));
                    asm volatile("st.shared.b32 [%0], %1;" :: "r"(ad1), "r"(*(uint32_t*)&h23));
                }
            }
        } else {
#pragma unroll
            for (int mt = 0; mt < 2; mt++) {
#pragma unroll
                for (int nt = 0; nt < 8; nt++) {
                    int r = m0 + wm + mt * 16 + g;
                    int c = wn + nt * 8 + 2 * t;
                    float bi0 = sb[768 + c], bi1 = sb[768 + c + 1];
                    __half2 h01 = __floats2half2_rn(acc[mt][nt][0] + bi0, acc[mt][nt][1] + bi1);
                    __half2 h23 = __floats2half2_rn(acc[mt][nt][2] + bi0, acc[mt][nt][3] + bi1);
                    *(__half2*)&qh[(size_t)r * KDIM + c]       = h01;
                    *(__half2*)&qh[(size_t)(r + 8) * KDIM + c] = h23;
                }
            }
        }
        __syncthreads();
    }
}

// ---------------------------------------------------------------------------
// Logits GEMM v6: mid-stage barrier + cross-barrier fragment prefetch.
// Stage kt (steady state; g0-frags of kt already in regs):
//   LDSM b0l | MMA g0(nt0-3) | LDSM a1,b1h | MMA g0(nt4-7) | LDSM b1l
//   STS A(kt+1) | LDG A(kt+2) | cp.async B(kt+3) | commit | wait_group 2
//   __syncthreads            <- stage kt+1 data published here
//   MMA g1(nt0-3) | LDSM g0(kt+1) (a0,b0h) | MMA g1(nt4-7)
// Every LDSM is covered by >=16 MMAs; barrier no longer heads a load burst.
// ---------------------------------------------------------------------------
#define LOG_SMEM (2 * 8192 + 4 * 8192)   // 49152

__global__ __launch_bounds__(256, 2)
void gemm_logits(const float* __restrict__ A, const __half* __restrict__ Bh,
                 float* __restrict__ C)
{
    extern __shared__ char sm[];
    char* As_ = sm;            // 2 x 8192
    char* Bs_ = sm + 16384;    // 4 x 8192

    const int tid = threadIdx.x;
    const int w = tid >> 5, l = tid & 31;
    const int g = l >> 2, t = l & 3;
    const int wm = (w & 3) * 32;
    const int wn = (w >> 2) * 64;

    const int nb = blockIdx.x;   // n-inner: nb pair shares the A tile via L2
    const int mb = blockIdx.y;
    const long long bb = blockIdx.z;

    const float* Ab = A + bb * ((long long)NF_ * KDIM) + (size_t)mb * 128 * KDIM;
    const __half* Bb = Bh + bb * ((long long)256 * KDIM) + (size_t)nb * 128 * KDIM;
    float* Cb = C + bb * ((long long)NF_ * 256) + (size_t)mb * 128 * 256 + (size_t)nb * 128;

    // ldmatrix A addrs (buf-relative)
    uint32_t a_addr[2];
    {
        int r = wm + (l & 7) + ((l >> 3) & 1) * 8;
        int ck = (l >> 4) & 1;
#pragma unroll
        for (int mt = 0; mt < 2; mt++) {
            int rr = r + mt * 16;
            int cp = (((rr >> 6) * 4 + ck) ^ (rr & 7));
            a_addr[mt] = cvta_s(As_ + (rr & 63) * 128 + cp * 16);
        }
    }
    // ldmatrix B addrs (slot-relative)
    uint32_t b_addr[4];
    {
        int n = wn + (l & 7) + ((l >> 4) & 1) * 8;
        int ck = (l >> 3) & 1;
#pragma unroll
        for (int p = 0; p < 4; p++) {
            int nn = n + p * 16;
            int cp = (((nn >> 6) * 4 + ck) ^ (nn & 7));
            b_addr[p] = cvta_s(Bs_ + (nn & 63) * 128 + cp * 16);
        }
    }
    // A STS addrs (buf-relative) + single gmem base
    const int fA = tid & 7;
    uint32_t sts_addr[4];
#pragma unroll
    for (int i = 0; i < 4; i++) {
        int r = i * 32 + (tid >> 3);
        int cp = (((r >> 6) * 4 + (fA >> 1)) ^ (r & 7));
        sts_addr[i] = cvta_s(As_ + (r & 63) * 128 + cp * 16 + (fA & 1) * 8);
    }
    const float* abase = Ab + (size_t)(tid >> 3) * KDIM + fA * 4;

    // B cp.async dsts (slot-relative) + single gmem base
    uint32_t bst0, bst1;
    {
        int n = tid >> 1, c = (tid & 1) * 2;
        bst0 = cvta_s(Bs_ + (n & 63) * 128 + ((((n >> 6) * 4) + c) ^ (n & 7)) * 16);
        bst1 = cvta_s(Bs_ + (n & 63) * 128 + ((((n >> 6) * 4) + c + 1) ^ (n & 7)) * 16);
    }
    const __half* bbase = Bb + (size_t)(tid >> 1) * KDIM + (tid & 1) * 16;

    // ---- prologue ----
    float4 pre[2][4];
#pragma unroll
    for (int i = 0; i < 4; i++) pre[0][i] = *(const float4*)(abase + (size_t)i * 32 * KDIM);
    CP16(bst0, bbase); CP16(bst1, bbase + 8);
    asm volatile("cp.async.commit_group;");
#pragma unroll
    for (int i = 0; i < 4; i++) pre[1][i] = *(const float4*)(abase + (size_t)i * 32 * KDIM + 32);
    CP16(bst0 + 8192, bbase + 32); CP16(bst1 + 8192, bbase + 40);
    asm volatile("cp.async.commit_group;");
    CP16(bst0 + 16384, bbase + 64); CP16(bst1 + 16384, bbase + 72);
    asm volatile("cp.async.commit_group;");

    // STS A(0)
#pragma unroll
    for (int i = 0; i < 4; i++) {
        __half2 h0 = __floats2half2_rn(pre[0][i].x, pre[0][i].y);
        __half2 h1 = __floats2half2_rn(pre[0][i].z, pre[0][i].w);
        asm volatile("st.shared.v2.b32 [%0], {%1,%2};"
                     :: "r"(sts_addr[i]), "r"(*(uint32_t*)&h0), "r"(*(uint32_t*)&h1));
    }

    float acc[2][8][4];
#pragma unroll
    for (int mt = 0; mt < 2; mt++)
#pragma unroll
        for (int nt = 0; nt < 8; nt++)
#pragma unroll
            for (int i = 0; i < 4; i++) acc[mt][nt][i] = 0.f;

    asm volatile("cp.async.wait_group 2;");   // B(0) resident
    __syncthreads();

    // prefetch g0(0)
    uint32_t a0[2][4], b0h[2][4];
    LDM4(a0[0][0], a0[0][1], a0[0][2], a0[0][3], a_addr[0]);
    LDM4(a0[1][0], a0[1][1], a0[1][2], a0[1][3], a_addr[1]);
    LDM4(b0h[0][0], b0h[0][1], b0h[0][2], b0h[0][3], b_addr[0]);
    LDM4(b0h[1][0], b0h[1][1], b0h[1][2], b0h[1][3], b_addr[1]);

#pragma unroll
    for (int kt = 0; kt < 8; kt++) {
        const uint32_t abuf = (kt & 1) * 8192;
        const uint32_t bbuf = (kt & 3) * 8192;

        // g0 second B half
        uint32_t b0l[2][4];
        LDM4(b0l[0][0], b0l[0][1], b0l[0][2], b0l[0][3], b_addr[2] + bbuf);
        LDM4(b0l[1][0], b0l[1][1], b0l[1][2], b0l[1][3], b_addr[3] + bbuf);

        // MMA g0 nt 0..3 (prefetched frags)
#pragma unroll
        for (int nt = 0; nt < 4; nt++) {
            uint32_t q0 = b0h[nt >> 1][(nt & 1) * 2];
            uint32_t q1 = b0h[nt >> 1][(nt & 1) * 2 + 1];
            MMA16(acc[0][nt], a0[0], q0, q1);
            MMA16(acc[1][nt], a0[1], q0, q1);
        }

        // g1 frags (first batch)
        uint32_t a1[2][4], b1h[2][4];
        LDM4(a1[0][0], a1[0][1], a1[0][2], a1[0][3], (a_addr[0] + abuf) ^ 32);
        LDM4(a1[1][0], a1[1][1], a1[1][2], a1[1][3], (a_addr[1] + abuf) ^ 32);
        LDM4(b1h[0][0], b1h[0][1], b1h[0][2], b1h[0][3], (b_addr[0] + bbuf) ^ 32);
        LDM4(b1h[1][0], b1h[1][1], b1h[1][2], b1h[1][3], (b_addr[1] + bbuf) ^ 32);

        // MMA g0 nt 4..7
#pragma unroll
        for (int nt = 4; nt < 8; nt++) {
            uint32_t q0 = b0l[(nt - 4) >> 1][(nt & 1) * 2];
            uint32_t q1 = b0l[(nt - 4) >> 1][(nt & 1) * 2 + 1];
            MMA16(acc[0][nt], a0[0], q0, q1);
            MMA16(acc[1][nt], a0[1], q0, q1);
        }

        // g1 second B half
        uint32_t b1l[2][4];
        LDM4(b1l[0][0], b1l[0][1], b1l[0][2], b1l[0][3], (b_addr[2] + bbuf) ^ 32);
        LDM4(b1l[1][0], b1l[1][1], b1l[1][2], b1l[1][3], (b_addr[3] + bbuf) ^ 32);

        // publish stage kt+1: STS A(kt+1), LDG A(kt+2), cp.async B(kt+3)
        if (kt < 7) {
            const uint32_t nab = ((kt + 1) & 1) * 8192;
#pragma unroll
            for (int i = 0; i < 4; i++) {
                __half2 h0 = __floats2half2_rn(pre[(kt + 1) & 1][i].x, pre[(kt + 1) & 1][i].y);
                __half2 h1 = __floats2half2_rn(pre[(kt + 1) & 1][i].z, pre[(kt + 1) & 1][i].w);
                asm volatile("st.shared.v2.b32 [%0], {%1,%2};"
                             :: "r"(sts_addr[i] + nab),
                                "r"(*(uint32_t*)&h0), "r"(*(uint32_t*)&h1));
            }
        }
        if (kt < 6) {
#pragma unroll
            for (int i = 0; i < 4; i++)
                pre[kt & 1][i] = *(const float4*)(abase + (size_t)i * 32 * KDIM + (kt + 2) * 32);
        }
        if (kt < 5) {
            const uint32_t ns = ((kt + 3) & 3) * 8192;
            CP16(bst0 + ns, bbase + (kt + 3) * 32);
            CP16(bst1 + ns, bbase + (kt + 3) * 32 + 8);
        }
        asm volatile("cp.async.commit_group;");
        asm volatile("cp.async.wait_group 2;");   // B(kt+1) landed

        __syncthreads();   // stage kt+1 data published; anti-deps ordered (see header)

        // MMA g1 nt 0..3
#pragma unroll
        for (int nt = 0; nt < 4; nt++) {
            uint32_t q0 = b1h[nt >> 1][(nt & 1) * 2];
            uint32_t q1 = b1h[nt >> 1][(nt & 1) * 2 + 1];
            MMA16(acc[0][nt], a1[0], q0, q1);
            MMA16(acc[1][nt], a1[1], q0, q1);
        }

        // prefetch g0(kt+1) — hidden behind the remaining g1 MMAs
        if (kt < 7) {
            const uint32_t nab = ((kt + 1) & 1) * 8192;
            const uint32_t nbb = ((kt + 1) & 3) * 8192;
            LDM4(a0[0][0], a0[0][1], a0[0][2], a0[0][3], a_addr[0] + nab);
            LDM4(a0[1][0], a0[1][1], a0[1][2], a0[1][3], a_addr[1] + nab);
            LDM4(b0h[0][0], b0h[0][1], b0h[0][2], b0h[0][3], b_addr[0] + nbb);
            LDM4(b0h[1][0], b0h[1][1], b0h[1][2], b0h[1][3], b_addr[1] + nbb);
        }

        // MMA g1 nt 4..7
#pragma unroll
        for (int nt = 4; nt < 8; nt++) {
            uint32_t q0 = b1l[(nt - 4) >> 1][(nt & 1) * 2];
            uint32_t q1 = b1l[(nt - 4) >> 1][(nt & 1) * 2 + 1];
            MMA16(acc[0][nt], a1[0], q0, q1);
            MMA16(acc[1][nt], a1[1], q0, q1);
        }
    }

    // ---- epilogue: streaming stores ----
#pragma unroll
    for (int mt = 0; mt < 2; mt++) {
        const int r0 = wm + mt * 16 + g;
#pragma unroll
        for (int nt = 0; nt < 8; nt++) {
            const int c = wn + nt * 8 + 2 * t;
            __stcs((float2*)&Cb[(size_t)r0 * 256 + c],
                   make_float2(acc[mt][nt][0], acc[mt][nt][1]));
            __stcs((float2*)&Cb[(size_t)(r0 + 8) * 256 + c],
                   make_float2(acc[mt][nt][2], acc[mt][nt][3]));
        }
    }
}

// ---------------------------------------------------------------------------
extern "C" void kernel_launch(void* const* d_in, const int* in_sizes, int n_in,
                              void* d_out, int out_size)
{
    (void)in_sizes; (void)n_in; (void)out_size;
    const float* queries = (const float*)d_in[0];
    const float* feats   = (const float*)d_in[1];
    const float* W1 = (const float*)d_in[4];
    const float* b1 = (const float*)d_in[5];
    const float* W2 = (const float*)d_in[6];
    const float* b2 = (const float*)d_in[7];
    const float* W3 = (const float*)d_in[8];
    const float* b3 = (const float*)d_in[9];
    const float* W4 = (const float*)d_in[10];
    const float* b4 = (const float*)d_in[11];
    float* out = (float*)d_out;

    __half *wh = nullptr, *qh = nullptr;
    cudaGetSymbolAddress((void**)&wh, g_wh);
    cudaGetSymbolAddress((void**)&qh, g_qh);

    cudaFuncSetAttribute(mlp_fused,   cudaFuncAttributeMaxDynamicSharedMemorySize, MLP_SMEM);
    cudaFuncSetAttribute(gemm_logits, cudaFuncAttributeMaxDynamicSharedMemorySize, LOG_SMEM);

    prep_w<<<256, 256>>>(W1, W2, W3, W4);
    mlp_fused<<<16, 256, MLP_SMEM>>>(queries, wh, b1, b2, b3, b4, qh);
    gemm_logits<<<dim3(2, NF_ / 128, B_), 256, LOG_SMEM>>>(feats, qh, out);
}